// round 5
// baseline (speedup 1.0000x reference)
#include <cuda_runtime.h>
#include <cstdint>

#define N_NODES_MAX 100000
#define N_EDGES_MAX 1700000
#define NFEAT 64
#define NCLASS 16
#define SCAN_B 512

// Scratch (device globals — no allocation allowed in kernel_launch).
__device__ int g_counts[N_NODES_MAX + 1];
__device__ int g_row_start[N_NODES_MAX + 1];
__device__ int g_cursor[N_NODES_MAX];
__device__ int g_csr_src[N_EDGES_MAX];
__device__ int g_bsum[1024];
__device__ int g_bpre[1024];

// ---------------------------------------------------------------------------
// CSR build: memset -> histogram(dst) -> 3-phase exclusive scan -> permute
// ---------------------------------------------------------------------------
__global__ void hist_kernel(const int* __restrict__ edge_index,
                            int* __restrict__ counts,
                            int n_edges, int n_nodes) {
    int e = blockIdx.x * blockDim.x + threadIdx.x;
    if (e >= n_edges) return;
    int dst = edge_index[n_edges + e];
    if ((unsigned)dst < (unsigned)n_nodes) atomicAdd(&counts[dst], 1);
}

__global__ void scan1_kernel(const int* __restrict__ counts,
                             int* __restrict__ bsum, int n) {
    __shared__ int sh[SCAN_B];
    int i = blockIdx.x * SCAN_B + threadIdx.x;
    sh[threadIdx.x] = (i < n) ? counts[i] : 0;
    __syncthreads();
    for (int off = SCAN_B / 2; off > 0; off >>= 1) {
        if (threadIdx.x < off) sh[threadIdx.x] += sh[threadIdx.x + off];
        __syncthreads();
    }
    if (threadIdx.x == 0) bsum[blockIdx.x] = sh[0];
}

// Parallel block-sum exclusive scan (single block, up to 1024 partials).
__global__ void scan2_kernel(const int* __restrict__ bsum,
                             int* __restrict__ bpre, int nb) {
    __shared__ int sh[1024];
    int t = threadIdx.x;
    int v = (t < nb) ? bsum[t] : 0;
    sh[t] = v;
    __syncthreads();
    for (int off = 1; off < 1024; off <<= 1) {
        int u = (t >= off) ? sh[t - off] : 0;
        __syncthreads();
        sh[t] += u;
        __syncthreads();
    }
    if (t < nb) bpre[t] = sh[t] - v;
}

__global__ void scan3_kernel(const int* __restrict__ counts,
                             const int* __restrict__ bpre,
                             int* __restrict__ row_start,
                             int* __restrict__ cursor, int n) {
    __shared__ int sh[SCAN_B];
    int i = blockIdx.x * SCAN_B + threadIdx.x;
    int v = (i < n) ? counts[i] : 0;
    sh[threadIdx.x] = v;
    __syncthreads();
    for (int off = 1; off < SCAN_B; off <<= 1) {
        int t = (threadIdx.x >= off) ? sh[threadIdx.x - off] : 0;
        __syncthreads();
        sh[threadIdx.x] += t;
        __syncthreads();
    }
    int excl = sh[threadIdx.x] - v + bpre[blockIdx.x];
    if (i < n) {
        row_start[i] = excl;
        cursor[i]    = excl;
        if (i == n - 1) row_start[n] = excl + v;
    }
}

__global__ void permute_kernel(const int* __restrict__ edge_index,
                               int* __restrict__ cursor,
                               int* __restrict__ csr_src,
                               int n_edges, int n_nodes) {
    int e = blockIdx.x * blockDim.x + threadIdx.x;
    if (e >= n_edges) return;
    int src = edge_index[e];
    int dst = edge_index[n_edges + e];
    if ((unsigned)src >= (unsigned)n_nodes || (unsigned)dst >= (unsigned)n_nodes) return;
    int pos = atomicAdd(&cursor[dst], 1);
    csr_src[pos] = src;
}

// ---------------------------------------------------------------------------
// Fused gather + MLP.  16 lanes per node:
//   phase 0: register gather of 4 feats/lane  (pull, no atomics)
//   phase 1: stage row in smem; lane computes 4 hidden units (LDS.128 weights)
//   phase 2: stage hidden; lane computes 1 class; coalesced STG
// Only half-warp syncs needed — writer set == reader set per node.
// ---------------------------------------------------------------------------
#define NPB 16          // nodes per block (256 threads / 16 lanes)
#define HPAD 68         // padded row (avoid cross-half bank conflicts)

__global__ __launch_bounds__(256)
void gather_mlp_kernel(const float* __restrict__ x,
                       const int* __restrict__ row_start,
                       const int* __restrict__ csr_src,
                       const float* __restrict__ eps,
                       const float* __restrict__ W1,   // [64,64] (k, j)
                       const float* __restrict__ b1,
                       const float* __restrict__ W2,   // [64,16] (j, c)
                       const float* __restrict__ b2,
                       float* __restrict__ out,
                       int n_nodes) {
    __shared__ float sW1[NFEAT * NFEAT];    // natural [k][j]
    __shared__ float sW2[NFEAT * NCLASS];   // natural [j][c]
    __shared__ float sb1[NFEAT];
    __shared__ float sb2[NCLASS];
    __shared__ float h_s[NPB][HPAD];
    __shared__ float hid_s[NPB][HPAD];

    for (int i = threadIdx.x; i < NFEAT * NFEAT; i += blockDim.x) sW1[i] = W1[i];
    for (int i = threadIdx.x; i < NFEAT * NCLASS; i += blockDim.x) sW2[i] = W2[i];
    if (threadIdx.x < NFEAT)  sb1[threadIdx.x] = b1[threadIdx.x];
    if (threadIdx.x < NCLASS) sb2[threadIdx.x] = b2[threadIdx.x];
    __syncthreads();

    const int half = threadIdx.x >> 4;        // node slot within block
    const int lane = threadIdx.x & 15;
    const unsigned hmask = ((threadIdx.x & 31) < 16) ? 0x0000FFFFu : 0xFFFF0000u;
    const int fg = lane << 2;
    const float s = 1.0f + *eps;
    const int stride = gridDim.x * NPB;

    for (int node = blockIdx.x * NPB + half; node < n_nodes; node += stride) {
        int beg = row_start[node];
        int end = row_start[node + 1];

        // --- gather: acc = (1+eps)*x[node][fg..] + sum_nbr x[src][fg..] ---
        float4 acc = *reinterpret_cast<const float4*>(x + (long long)node * NFEAT + fg);
        acc.x *= s; acc.y *= s; acc.z *= s; acc.w *= s;

        for (int e = beg; e < end; ) {
            int cnt = min(16, end - e);
            int id = (lane < cnt) ? csr_src[e + lane] : 0;
#pragma unroll 4
            for (int j = 0; j < cnt; j++) {
                int src = __shfl_sync(hmask, id, j, 16);
                float4 v = *reinterpret_cast<const float4*>(x + (long long)src * NFEAT + fg);
                acc.x += v.x; acc.y += v.y; acc.z += v.z; acc.w += v.w;
            }
            e += cnt;
        }

        // --- stage row (guard previous iteration's readers) ---
        __syncwarp(hmask);
        *reinterpret_cast<float4*>(&h_s[half][fg]) = acc;
        __syncwarp(hmask);

        // --- layer 1: lane owns hidden[fg..fg+3] ---
        float4 hid = make_float4(sb1[fg], sb1[fg + 1], sb1[fg + 2], sb1[fg + 3]);
#pragma unroll 8
        for (int k = 0; k < NFEAT; k++) {
            float hk = h_s[half][k];                             // broadcast
            float4 w = *reinterpret_cast<const float4*>(&sW1[k * NFEAT + fg]);
            hid.x = fmaf(hk, w.x, hid.x);
            hid.y = fmaf(hk, w.y, hid.y);
            hid.z = fmaf(hk, w.z, hid.z);
            hid.w = fmaf(hk, w.w, hid.w);
        }
        hid.x = fmaxf(hid.x, 0.f); hid.y = fmaxf(hid.y, 0.f);
        hid.z = fmaxf(hid.z, 0.f); hid.w = fmaxf(hid.w, 0.f);
        *reinterpret_cast<float4*>(&hid_s[half][fg]) = hid;
        __syncwarp(hmask);

        // --- layer 2: lane owns class c = lane ---
        float o = sb2[lane];
#pragma unroll 8
        for (int j = 0; j < NFEAT; j++)
            o = fmaf(hid_s[half][j], sW2[j * NCLASS + lane], o);

        out[(long long)node * NCLASS + lane] = o;
    }
}

// ---------------------------------------------------------------------------
// Launch.  Inputs (metadata order): x, edge_index(int32), eps, W1, b1, W2, b2
// ---------------------------------------------------------------------------
extern "C" void kernel_launch(void* const* d_in, const int* in_sizes, int n_in,
                              void* d_out, int out_size) {
    const float* x   = (const float*)d_in[0];
    const int*   ei  = (const int*)d_in[1];
    const float* eps = (const float*)d_in[2];
    const float* W1  = (const float*)d_in[3];
    const float* b1  = (const float*)d_in[4];
    const float* W2  = (const float*)d_in[5];
    const float* b2  = (const float*)d_in[6];
    float*       out = (float*)d_out;

    int n_nodes = in_sizes[0] / NFEAT;
    int n_edges = in_sizes[1] / 2;

    int *counts, *row_start, *cursor, *csr_src, *bsum, *bpre;
    cudaGetSymbolAddress((void**)&counts,    g_counts);
    cudaGetSymbolAddress((void**)&row_start, g_row_start);
    cudaGetSymbolAddress((void**)&cursor,    g_cursor);
    cudaGetSymbolAddress((void**)&csr_src,   g_csr_src);
    cudaGetSymbolAddress((void**)&bsum,      g_bsum);
    cudaGetSymbolAddress((void**)&bpre,      g_bpre);

    int nb = (n_nodes + SCAN_B - 1) / SCAN_B;

    // --- CSR build ---
    cudaMemsetAsync(counts, 0, (size_t)n_nodes * sizeof(int));
    hist_kernel<<<(n_edges + 255) / 256, 256>>>(ei, counts, n_edges, n_nodes);
    scan1_kernel<<<nb, SCAN_B>>>(counts, bsum, n_nodes);
    scan2_kernel<<<1, 1024>>>(bsum, bpre, nb);
    scan3_kernel<<<nb, SCAN_B>>>(counts, bpre, row_start, cursor, n_nodes);
    permute_kernel<<<(n_edges + 255) / 256, 256>>>(ei, cursor, csr_src, n_edges, n_nodes);

    // --- fused aggregation + MLP ---
    gather_mlp_kernel<<<1480, 256>>>(x, row_start, csr_src, eps,
                                     W1, b1, W2, b2, out, n_nodes);
}